// round 7
// baseline (speedup 1.0000x reference)
#include <cuda_runtime.h>
#include <math.h>

#define N_RESV 384
#define CSV    384
#define CZV    128
#define NHV    12
#define CHV    16
#define NQPV   4
#define NPVV   8
#define DPROJ  1152
#define DCAT   2112
#define NROWS  (N_RESV * N_RESV)
#define SPLITK 4
#define KSLICE (DCAT / SPLITK)   // 528

typedef unsigned long long ull;

__device__ __forceinline__ ull pack2(float x, float y) {
    ull r; asm("mov.b64 %0, {%1,%2};" : "=l"(r) : "f"(x), "f"(y)); return r;
}
__device__ __forceinline__ ull ffma2(ull a, ull b, ull c) {
    ull d; asm("fma.rn.f32x2 %0, %1, %2, %3;" : "=l"(d) : "l"(a), "l"(b), "l"(c)); return d;
}
__device__ __forceinline__ float2 unpack2(ull p) {
    float x, y; asm("mov.b64 {%0,%1}, %2;" : "=f"(x), "=f"(y) : "l"(p));
    return make_float2(x, y);
}

// ---------------- scratch ----------------------------------------------------
__device__ float g_Wcat[CSV * DPROJ];
__device__ float g_bcat[DPROJ];
__device__ float g_raw [N_RESV * DPROJ];
__device__ float g_q [NHV * N_RESV * CHV];
__device__ float g_k [NHV * N_RESV * CHV];
__device__ float g_v [NHV * N_RESV * CHV];
__device__ float g_tqp[NHV * NQPV * N_RESV * 3];
__device__ float g_tkp[NHV * NQPV * N_RESV * 3];
__device__ float g_tvp[NHV * NPVV * N_RESV * 3];
__device__ float g_bias[NHV * NROWS];
__device__ float g_att [NHV * NROWS];
__device__ float g_av  [NHV * N_RESV * 40];
__device__ float g_concat[N_RESV * DCAT];
__device__ float g_part[SPLITK * N_RESV * N_RESV];

// ---------------- kernel 1: build concatenated projection weights ------------
__global__ void build_wcat_kernel(
    const float* Wq, const float* bq, const float* Wk, const float* bk,
    const float* Wv, const float* bv, const float* Wqp, const float* bqp,
    const float* Wkp, const float* bkp, const float* Wvp, const float* bvp)
{
    int idx = blockIdx.x * blockDim.x + threadIdx.x;
    int stride = gridDim.x * blockDim.x;
    const int total = CSV * DPROJ;
    for (int t = idx; t < total; t += stride) {
        int c = t / DPROJ, d = t % DPROJ;
        float v;
        if      (d < 192)  v = Wq [c * 192 + d];
        else if (d < 384)  v = Wk [c * 192 + (d - 192)];
        else if (d < 576)  v = Wv [c * 192 + (d - 384)];
        else if (d < 720)  v = Wqp[c * 144 + (d - 576)];
        else if (d < 864)  v = Wkp[c * 144 + (d - 720)];
        else               v = Wvp[c * 288 + (d - 864)];
        g_Wcat[t] = v;
    }
    for (int d = idx; d < DPROJ; d += stride) {
        float v;
        if      (d < 192)  v = bq [d];
        else if (d < 384)  v = bk [d - 192];
        else if (d < 576)  v = bv [d - 384];
        else if (d < 720)  v = bqp[d - 576];
        else if (d < 864)  v = bkp[d - 720];
        else               v = bvp[d - 864];
        g_bcat[d] = v;
    }
}

// ---------- GEMM 32x64 tile, 2x4 per thread, 256 threads (proj) --------------
__global__ void gemm32_kernel(const float* __restrict__ A, int lda,
                              const float* __restrict__ W, int ldw,
                              const float* __restrict__ bias,
                              float* __restrict__ C, int ldc, int K)
{
    __shared__ float sA[16][36];
    __shared__ float sB[16][68];
    int i0 = blockIdx.x * 32;
    int o0 = blockIdx.y * 64;

    int t  = threadIdx.x;
    int tc = t & 15;
    int tr = t >> 4;

    int ar = t >> 2;
    int ak = (t & 3) * 4;
    int bk = t >> 4;
    int bn = (t & 15) * 4;

    ull acc2[2][2];
    acc2[0][0] = acc2[0][1] = acc2[1][0] = acc2[1][1] = 0ull;

    for (int kk = 0; kk < K; kk += 16) {
        __syncthreads();
        if (t < 128) {
            float4 av = *(const float4*)&A[(size_t)(i0 + ar) * lda + kk + ak];
            sA[ak + 0][ar] = av.x;
            sA[ak + 1][ar] = av.y;
            sA[ak + 2][ar] = av.z;
            sA[ak + 3][ar] = av.w;
        }
        float4 bv = *(const float4*)&W[(size_t)(kk + bk) * ldw + o0 + bn];
        *(float4*)&sB[bk][bn] = bv;
        __syncthreads();
#pragma unroll
        for (int k = 0; k < 16; k++) {
            float2 a = *(const float2*)&sA[k][tr * 2];
            ulonglong2 b2 = *(const ulonglong2*)&sB[k][tc * 4];
            ull a0 = pack2(a.x, a.x);
            ull a1 = pack2(a.y, a.y);
            acc2[0][0] = ffma2(a0, b2.x, acc2[0][0]);
            acc2[0][1] = ffma2(a0, b2.y, acc2[0][1]);
            acc2[1][0] = ffma2(a1, b2.x, acc2[1][0]);
            acc2[1][1] = ffma2(a1, b2.y, acc2[1][1]);
        }
    }

    const float* bp = &bias[o0 + tc * 4];
    float4 bb4 = *(const float4*)bp;
#pragma unroll
    for (int i = 0; i < 2; i++) {
        float2 lo = unpack2(acc2[i][0]);
        float2 hi = unpack2(acc2[i][1]);
        float* crow = &C[(size_t)(i0 + tr * 2 + i) * ldc + o0 + tc * 4];
        *(float4*)crow = make_float4(lo.x + bb4.x, lo.y + bb4.y,
                                     hi.x + bb4.z, hi.y + bb4.w);
    }
}

// ---------- register-tiled GEMM: 64x64 tile, 4x4 per thread (final) ----------
__global__ void gemm64_kernel(const float* __restrict__ A, int lda,
                              const float* __restrict__ W, int ldw,
                              float* __restrict__ C, int ldc, int kLen)
{
    __shared__ float sA[16][68];
    __shared__ float sB[16][68];
    int i0 = blockIdx.x * 64;
    int o0 = blockIdx.y * 64;
    int k0 = blockIdx.z * kLen;
    C += (size_t)blockIdx.z * (size_t)(gridDim.x * 64) * ldc;

    int t  = threadIdx.x;
    int tc = t & 15;
    int tr = t >> 4;

    int ar = t >> 2;
    int ak = (t & 3) * 4;
    int bk = t >> 4;
    int bn = (t & 15) * 4;

    ull acc2[4][2];
#pragma unroll
    for (int i = 0; i < 4; i++) { acc2[i][0] = 0ull; acc2[i][1] = 0ull; }

    for (int kk = 0; kk < kLen; kk += 16) {
        __syncthreads();
        float4 av = *(const float4*)&A[(size_t)(i0 + ar) * lda + k0 + kk + ak];
        sA[ak + 0][ar] = av.x;
        sA[ak + 1][ar] = av.y;
        sA[ak + 2][ar] = av.z;
        sA[ak + 3][ar] = av.w;
        float4 bv = *(const float4*)&W[(size_t)(k0 + kk + bk) * ldw + o0 + bn];
        *(float4*)&sB[bk][bn] = bv;
        __syncthreads();
#pragma unroll
        for (int k = 0; k < 16; k++) {
            float4 a = *(const float4*)&sA[k][tr * 4];
            ulonglong2 b2 = *(const ulonglong2*)&sB[k][tc * 4];
            ull a0 = pack2(a.x, a.x);
            ull a1 = pack2(a.y, a.y);
            ull a2 = pack2(a.z, a.z);
            ull a3 = pack2(a.w, a.w);
            acc2[0][0] = ffma2(a0, b2.x, acc2[0][0]);
            acc2[0][1] = ffma2(a0, b2.y, acc2[0][1]);
            acc2[1][0] = ffma2(a1, b2.x, acc2[1][0]);
            acc2[1][1] = ffma2(a1, b2.y, acc2[1][1]);
            acc2[2][0] = ffma2(a2, b2.x, acc2[2][0]);
            acc2[2][1] = ffma2(a2, b2.y, acc2[2][1]);
            acc2[3][0] = ffma2(a3, b2.x, acc2[3][0]);
            acc2[3][1] = ffma2(a3, b2.y, acc2[3][1]);
        }
    }

#pragma unroll
    for (int i = 0; i < 4; i++) {
        float2 lo = unpack2(acc2[i][0]);
        float2 hi = unpack2(acc2[i][1]);
        float* crow = &C[(size_t)(i0 + tr * 4 + i) * ldc + o0 + tc * 4];
        *(float4*)crow = make_float4(lo.x, lo.y, hi.x, hi.y);
    }
}

// ---------------- split-K reduce + bias (float4) -----------------------------
__global__ void reduce_kernel(const float* __restrict__ bias,
                              float* __restrict__ out)
{
    int idx = blockIdx.x * blockDim.x + threadIdx.x;
    if (idx >= NROWS / 4) return;
    const float4* p = (const float4*)g_part;
    float4 a = p[idx];
    float4 b = p[idx + NROWS / 4];
    float4 c = p[idx + NROWS / 2];
    float4 d = p[idx + 3 * NROWS / 4];
    int col = (idx % (N_RESV / 4)) * 4;
    float4 bv = *(const float4*)&bias[col];
    float4 o;
    o.x = a.x + b.x + c.x + d.x + bv.x;
    o.y = a.y + b.y + c.y + d.y + bv.y;
    o.z = a.z + b.z + c.z + d.z + bv.z;
    o.w = a.w + b.w + c.w + d.w + bv.w;
    ((float4*)out)[idx] = o;
}

// ---------------- kernel 3: scatter projections + transform points -----------
__global__ void scatter_kernel(const float* __restrict__ T)
{
    int i = blockIdx.x;
    const float* raw = g_raw + (size_t)i * DPROJ;
    const float* Ti  = T + (size_t)i * 16;

    for (int t = threadIdx.x; t < 768; t += blockDim.x) {
        if (t < 576) {
            int kind = t / 192, d = t % 192;
            int h = d / 16, c = d % 16;
            float v = raw[kind * 192 + d];
            if (kind == 0) v *= 0.25f;
            float* dst = (kind == 0) ? g_q : ((kind == 1) ? g_k : g_v);
            dst[(h * N_RESV + i) * CHV + c] = v;
        } else {
            int t2 = t - 576;
            int kind, hp, P, base;
            if      (t2 < 48)  { kind = 0; hp = t2;       P = NQPV; base = 576; }
            else if (t2 < 96)  { kind = 1; hp = t2 - 48;  P = NQPV; base = 720; }
            else               { kind = 2; hp = t2 - 96;  P = NPVV; base = 864; }
            int HP = NHV * P;
            float px = raw[base + 0 * HP + hp];
            float py = raw[base + 1 * HP + hp];
            float pz = raw[base + 2 * HP + hp];
            float ox = Ti[0] * px + Ti[1] * py + Ti[2]  * pz + Ti[3];
            float oy = Ti[4] * px + Ti[5] * py + Ti[6]  * pz + Ti[7];
            float oz = Ti[8] * px + Ti[9] * py + Ti[10] * pz + Ti[11];
            float* dst = (kind == 0) ? g_tqp : ((kind == 1) ? g_tkp : g_tvp);
            float* o = dst + ((size_t)hp * N_RESV + i) * 3;
            o[0] = ox; o[1] = oy; o[2] = oz;
        }
    }
}

// ---------------- kernel 4: bias = z @ Wb + bb (head-split, high occupancy) --
// grid (1152, 2), block 128; 128 rows/block, 1 row/thread, 6 heads/block.
__global__ void bias_gemm_kernel(const float* __restrict__ z,
                                 const float* __restrict__ Wb,
                                 const float* __restrict__ bb)
{
    __shared__ float2 sz[128 * 17];          // 17-float2 pitch
    __shared__ ull    swp[6 * 64];           // packed Wb pairs [h][q], 6 heads
    int t = threadIdx.x;
    int r0 = blockIdx.x * 128;
    int h0 = blockIdx.y * 6;

    for (int idx = t; idx < 6 * 64; idx += 128) {
        int h = idx >> 6, q = idx & 63;
        swp[idx] = pack2(Wb[(2 * q) * NHV + h0 + h], Wb[(2 * q + 1) * NHV + h0 + h]);
    }

    ull acc[6];
#pragma unroll
    for (int h = 0; h < 6; h++) acc[h] = 0ull;

    for (int ct = 0; ct < CZV; ct += 32) {
        __syncthreads();
        for (int idx = t; idx < 2048; idx += 128) {
            int row = idx >> 4, q = idx & 15;
            sz[row * 17 + q] = *(const float2*)&z[(size_t)(r0 + row) * CZV + ct + 2 * q];
        }
        __syncthreads();
        const float2* zrow = &sz[t * 17];
        int cbase = ct >> 1;
#pragma unroll
        for (int q = 0; q < 16; q++) {
            ull zp = *reinterpret_cast<const ull*>(&zrow[q]);
#pragma unroll
            for (int h = 0; h < 6; h++)
                acc[h] = ffma2(zp, swp[h * 64 + cbase + q], acc[h]);
        }
    }
    int row = r0 + t;
#pragma unroll
    for (int h = 0; h < 6; h++) {
        float2 v = unpack2(acc[h]);
        g_bias[(size_t)(h0 + h) * NROWS + row] = v.x + v.y + bb[h0 + h];
    }
}

// ---------------- kernel 5: logits + softmax. grid (48, 12), block 256 -------
__global__ void att_kernel(const float* __restrict__ head_weights)
{
    int h = blockIdx.y;
    int i0 = blockIdx.x * 8;
    __shared__ float sk [32][17];
    __shared__ float skp[32][12];
    __shared__ float sq [8][16];
    __shared__ float sqp[8][12];
    __shared__ float slog[8][N_RESV];

    int t = threadIdx.x, w = t >> 5, lane = t & 31;

    if (t < 128) {
        int iw = t / 16, c = t % 16;
        sq[iw][c] = g_q[(h * N_RESV + i0 + iw) * CHV + c];
    }
    if (t < 96) {
        int iw = t / 12, u = t % 12, p = u / 3, d = u % 3;
        sqp[iw][u] = g_tqp[((h * NQPV + p) * N_RESV + i0 + iw) * 3 + d];
    }
    float hw = head_weights[h];
    float gamma = (hw > 20.f) ? hw : log1pf(expf(hw));
    const float wc = 0.23570226039551584f;
    const float wl = 0.57735026918962576f;
    float coef = gamma * wc * 0.5f;

    const float* brow = &g_bias[(size_t)h * NROWS + (size_t)(i0 + w) * N_RESV];

    for (int j0 = 0; j0 < N_RESV; j0 += 32) {
        __syncthreads();
        for (int idx = t; idx < 32 * 16; idx += 256)
            sk[idx >> 4][idx & 15] = g_k[(h * N_RESV + j0 + (idx >> 4)) * CHV + (idx & 15)];
        for (int idx = t; idx < 32 * 12; idx += 256) {
            int j = idx / 12, u = idx % 12, p = u / 3, d = u % 3;
            skp[j][u] = g_tkp[((h * NQPV + p) * N_RESV + j0 + j) * 3 + d];
        }
        __syncthreads();
        int j = j0 + lane;
        float qk = 0.f;
#pragma unroll
        for (int c = 0; c < CHV; c++) qk = fmaf(sq[w][c], sk[lane][c], qk);
        float d2 = 0.f;
#pragma unroll
        for (int p = 0; p < NQPV; p++) {
            float dx = sqp[w][p * 3 + 0] - skp[lane][p * 3 + 0];
            float dy = sqp[w][p * 3 + 1] - skp[lane][p * 3 + 1];
            float dz = sqp[w][p * 3 + 2] - skp[lane][p * 3 + 2];
            d2 += dx * dx + dy * dy + dz * dz;
        }
        slog[w][j] = wl * (qk + brow[j] - coef * d2);
    }

    float m = -1e30f;
#pragma unroll
    for (int r = 0; r < 12; r++) m = fmaxf(m, slog[w][lane + r * 32]);
#pragma unroll
    for (int o = 16; o; o >>= 1) m = fmaxf(m, __shfl_xor_sync(0xffffffffu, m, o));
    float ssum = 0.f;
#pragma unroll
    for (int r = 0; r < 12; r++) {
        float e = expf(slog[w][lane + r * 32] - m);
        slog[w][lane + r * 32] = e;
        ssum += e;
    }
#pragma unroll
    for (int o = 16; o; o >>= 1) ssum += __shfl_xor_sync(0xffffffffu, ssum, o);
    float inv = 1.f / ssum;
    float* arow = &g_att[(size_t)h * NROWS + (size_t)(i0 + w) * N_RESV];
#pragma unroll
    for (int r = 0; r < 12; r++) arow[lane + r * 32] = slog[w][lane + r * 32] * inv;
}

// ---------------- kernel 6: per-head GEMM  att[h] @ [v|vp], f32x2 ------------
// grid (12, 12) = 144 blocks, block 320; tile 32 rows x 40 cols; 4 cols/thread.
__global__ void att_av_kernel()
{
    int h = blockIdx.y;
    int i0 = blockIdx.x * 32;
    __shared__ float satt[32][65];
    __shared__ float sx[64][44];
    int t = threadIdx.x;
    int r  = t / 10;
    int c0 = (t % 10) * 4;
    ull acc2[2];
    acc2[0] = 0ull; acc2[1] = 0ull;

    for (int j0 = 0; j0 < N_RESV; j0 += 64) {
        __syncthreads();
        for (int idx = t; idx < 32 * 16; idx += 320) {
            int row = idx >> 4, v4 = idx & 15;
            float4 v = *(const float4*)&g_att[((size_t)h * N_RESV + i0 + row) * N_RESV + j0 + v4 * 4];
            float* dst = &satt[row][v4 * 4];
            dst[0] = v.x; dst[1] = v.y; dst[2] = v.z; dst[3] = v.w;
        }
        for (int idx = t; idx < 64 * 40; idx += 320) {
            int j = idx / 40, col = idx % 40;
            float v;
            if (col < 16) v = g_v[(h * N_RESV + j0 + j) * CHV + col];
            else {
                int u = col - 16, p = u / 3, d = u % 3;
                v = g_tvp[((h * NPVV + p) * N_RESV + j0 + j) * 3 + d];
            }
            sx[j][col] = v;
        }
        __syncthreads();
#pragma unroll 4
        for (int jj = 0; jj < 64; jj++) {
            float a = satt[r][jj];
            ull ap = pack2(a, a);
            ulonglong2 xr = *(const ulonglong2*)&sx[jj][c0];
            acc2[0] = ffma2(ap, xr.x, acc2[0]);
            acc2[1] = ffma2(ap, xr.y, acc2[1]);
        }
    }
    float2 lo = unpack2(acc2[0]);
    float2 hi = unpack2(acc2[1]);
    float* orow = &g_av[((size_t)h * N_RESV + i0 + r) * 40 + c0];
    *(float4*)orow = make_float4(lo.x, lo.y, hi.x, hi.y);
}

// ---------------- kernel 7: pairwise GEMM + finalize (direct-LDG, f32x2) -----
__global__ void out_kernel(const float* __restrict__ z,
                           const float* __restrict__ T)
{
    int i = blockIdx.x;
    __shared__ float att[NHV][N_RESV];
    int t = threadIdx.x;

    for (int idx = t; idx < NHV * N_RESV / 4; idx += 384) {
        int h = idx / (N_RESV / 4), q = idx % (N_RESV / 4);
        float4 v = *(const float4*)&g_att[((size_t)h * N_RESV + i) * N_RESV + q * 4];
        *(float4*)&att[h][q * 4] = v;
    }
    __syncthreads();

    int h  = t >> 5;
    int c4 = t & 31;
    const ulonglong2* zbase = (const ulonglong2*)(z + (size_t)i * N_RESV * CZV) + c4;
    const float* arow = att[h];

    ull acc01 = 0ull, acc23 = 0ull;
#pragma unroll 8
    for (int j = 0; j < N_RESV; j++) {
        float a = arow[j];
        ull ap = pack2(a, a);
        ulonglong2 zp = __ldg(zbase + (size_t)j * 32);
        acc01 = ffma2(ap, zp.x, acc01);
        acc23 = ffma2(ap, zp.y, acc23);
    }
    float2 lo = unpack2(acc01);
    float2 hi = unpack2(acc23);
    float* crow = g_concat + (size_t)i * DCAT;
    *(float4*)&crow[576 + h * CZV + c4 * 4] = make_float4(lo.x, lo.y, hi.x, hi.y);

    if (t < 192) {
        int hh = t / 16, cc = t % 16;
        crow[hh * 16 + cc] = g_av[((size_t)hh * N_RESV + i) * 40 + cc];
    }
    const float* Ti = T + (size_t)i * 16;
    if (t < 96) {
        int hh = t / 8, p = t % 8;
        const float* av = &g_av[((size_t)hh * N_RESV + i) * 40 + 16 + p * 3];
        float px = av[0] - Ti[3];
        float py = av[1] - Ti[7];
        float pz = av[2] - Ti[11];
        float ox = Ti[0] * px + Ti[4] * py + Ti[8]  * pz;
        float oy = Ti[1] * px + Ti[5] * py + Ti[9]  * pz;
        float oz = Ti[2] * px + Ti[6] * py + Ti[10] * pz;
        crow[192 +   0 + hh * 8 + p] = ox;
        crow[192 +  96 + hh * 8 + p] = oy;
        crow[192 + 192 + hh * 8 + p] = oz;
        crow[480 + hh * 8 + p] = sqrtf(ox * ox + oy * oy + oz * oz);
    }
}

// ---------------- launch ------------------------------------------------------
extern "C" void kernel_launch(void* const* d_in, const int* in_sizes, int n_in,
                              void* d_out, int out_size)
{
    const float* s   = (const float*)d_in[0];
    const float* z   = (const float*)d_in[1];
    const float* T   = (const float*)d_in[2];
    const float* Wq  = (const float*)d_in[3];
    const float* bq  = (const float*)d_in[4];
    const float* Wk  = (const float*)d_in[5];
    const float* bk  = (const float*)d_in[6];
    const float* Wv  = (const float*)d_in[7];
    const float* bv  = (const float*)d_in[8];
    const float* Wqp = (const float*)d_in[9];
    const float* bqp = (const float*)d_in[10];
    const float* Wkp = (const float*)d_in[11];
    const float* bkp = (const float*)d_in[12];
    const float* Wvp = (const float*)d_in[13];
    const float* bvp = (const float*)d_in[14];
    const float* Wb  = (const float*)d_in[15];
    const float* bb  = (const float*)d_in[16];
    const float* Wo  = (const float*)d_in[17];
    const float* bo  = (const float*)d_in[18];
    const float* hwt = (const float*)d_in[19];

    float* out = (float*)d_out;

    float* raw_p;    cudaGetSymbolAddress((void**)&raw_p,    g_raw);
    float* wcat_p;   cudaGetSymbolAddress((void**)&wcat_p,   g_Wcat);
    float* bcat_p;   cudaGetSymbolAddress((void**)&bcat_p,   g_bcat);
    float* concat_p; cudaGetSymbolAddress((void**)&concat_p, g_concat);
    float* part_p;   cudaGetSymbolAddress((void**)&part_p,   g_part);

    build_wcat_kernel<<<432, 256>>>(Wq, bq, Wk, bk, Wv, bv,
                                    Wqp, bqp, Wkp, bkp, Wvp, bvp);

    gemm32_kernel<<<dim3(N_RESV / 32, DPROJ / 64), 256>>>(
        s, CSV, wcat_p, DPROJ, bcat_p, raw_p, DPROJ, CSV);

    scatter_kernel<<<N_RESV, 256>>>(T);

    bias_gemm_kernel<<<dim3(NROWS / 128, 2), 128>>>(z, Wb, bb);

    att_kernel<<<dim3(48, NHV), 256>>>(hwt);

    att_av_kernel<<<dim3(12, NHV), 320>>>();

    out_kernel<<<N_RESV, 384>>>(z, T);

    gemm64_kernel<<<dim3(N_RESV / 64, N_RESV / 64, SPLITK), 256>>>(
        concat_p, DCAT, Wo, CSV, part_p, CSV, KSLICE);

    reduce_kernel<<<(NROWS / 4 + 255) / 256, 256>>>(bo, out);
}

// round 8
// speedup vs baseline: 1.0808x; 1.0808x over previous
#include <cuda_runtime.h>
#include <math.h>

#define N_RESV 384
#define CSV    384
#define CZV    128
#define NHV    12
#define CHV    16
#define NQPV   4
#define NPVV   8
#define DPROJ  1152
#define DCAT   2112
#define NROWS  (N_RESV * N_RESV)
#define SPLITK 4
#define KSLICE (DCAT / SPLITK)   // 528

typedef unsigned long long ull;

__device__ __forceinline__ ull pack2(float x, float y) {
    ull r; asm("mov.b64 %0, {%1,%2};" : "=l"(r) : "f"(x), "f"(y)); return r;
}
__device__ __forceinline__ ull ffma2(ull a, ull b, ull c) {
    ull d; asm("fma.rn.f32x2 %0, %1, %2, %3;" : "=l"(d) : "l"(a), "l"(b), "l"(c)); return d;
}
__device__ __forceinline__ float2 unpack2(ull p) {
    float x, y; asm("mov.b64 {%0,%1}, %2;" : "=f"(x), "=f"(y) : "l"(p));
    return make_float2(x, y);
}

// ---------------- scratch ----------------------------------------------------
__device__ float g_Wcat[CSV * DPROJ];
__device__ float g_bcat[DPROJ];
__device__ float g_raw [N_RESV * DPROJ];
__device__ float g_q [NHV * N_RESV * CHV];
__device__ float g_k [NHV * N_RESV * CHV];
__device__ float g_v [NHV * N_RESV * CHV];
__device__ float g_tqp[NHV * NQPV * N_RESV * 3];
__device__ float g_tkp[NHV * NQPV * N_RESV * 3];
__device__ float g_tvp[NHV * NPVV * N_RESV * 3];
__device__ float g_bias[NHV * NROWS];
__device__ float g_att [NHV * NROWS];
__device__ float g_av  [NHV * N_RESV * 40];
__device__ float g_concat[N_RESV * DCAT];
__device__ float g_part[SPLITK * N_RESV * N_RESV];

// ---------------- kernel 1: build concatenated projection weights ------------
__global__ void build_wcat_kernel(
    const float* Wq, const float* bq, const float* Wk, const float* bk,
    const float* Wv, const float* bv, const float* Wqp, const float* bqp,
    const float* Wkp, const float* bkp, const float* Wvp, const float* bvp)
{
    int idx = blockIdx.x * blockDim.x + threadIdx.x;
    int stride = gridDim.x * blockDim.x;
    const int total = CSV * DPROJ;
    for (int t = idx; t < total; t += stride) {
        int c = t / DPROJ, d = t % DPROJ;
        float v;
        if      (d < 192)  v = Wq [c * 192 + d];
        else if (d < 384)  v = Wk [c * 192 + (d - 192)];
        else if (d < 576)  v = Wv [c * 192 + (d - 384)];
        else if (d < 720)  v = Wqp[c * 144 + (d - 576)];
        else if (d < 864)  v = Wkp[c * 144 + (d - 720)];
        else               v = Wvp[c * 288 + (d - 864)];
        g_Wcat[t] = v;
    }
    for (int d = idx; d < DPROJ; d += stride) {
        float v;
        if      (d < 192)  v = bq [d];
        else if (d < 384)  v = bk [d - 192];
        else if (d < 576)  v = bv [d - 384];
        else if (d < 720)  v = bqp[d - 576];
        else if (d < 864)  v = bkp[d - 720];
        else               v = bvp[d - 864];
        g_bcat[d] = v;
    }
}

// ---------- GEMM 32x64 tile, 2x4 per thread, 256 threads (proj) --------------
__global__ void gemm32_kernel(const float* __restrict__ A, int lda,
                              const float* __restrict__ W, int ldw,
                              const float* __restrict__ bias,
                              float* __restrict__ C, int ldc, int K)
{
    __shared__ float sA[16][36];
    __shared__ float sB[16][68];
    int i0 = blockIdx.x * 32;
    int o0 = blockIdx.y * 64;

    int t  = threadIdx.x;
    int tc = t & 15;
    int tr = t >> 4;

    int ar = t >> 2;
    int ak = (t & 3) * 4;
    int bk = t >> 4;
    int bn = (t & 15) * 4;

    ull acc2[2][2];
    acc2[0][0] = acc2[0][1] = acc2[1][0] = acc2[1][1] = 0ull;

    for (int kk = 0; kk < K; kk += 16) {
        __syncthreads();
        if (t < 128) {
            float4 av = *(const float4*)&A[(size_t)(i0 + ar) * lda + kk + ak];
            sA[ak + 0][ar] = av.x;
            sA[ak + 1][ar] = av.y;
            sA[ak + 2][ar] = av.z;
            sA[ak + 3][ar] = av.w;
        }
        float4 bv = *(const float4*)&W[(size_t)(kk + bk) * ldw + o0 + bn];
        *(float4*)&sB[bk][bn] = bv;
        __syncthreads();
#pragma unroll
        for (int k = 0; k < 16; k++) {
            float2 a = *(const float2*)&sA[k][tr * 2];
            ulonglong2 b2 = *(const ulonglong2*)&sB[k][tc * 4];
            ull a0 = pack2(a.x, a.x);
            ull a1 = pack2(a.y, a.y);
            acc2[0][0] = ffma2(a0, b2.x, acc2[0][0]);
            acc2[0][1] = ffma2(a0, b2.y, acc2[0][1]);
            acc2[1][0] = ffma2(a1, b2.x, acc2[1][0]);
            acc2[1][1] = ffma2(a1, b2.y, acc2[1][1]);
        }
    }

    const float* bp = &bias[o0 + tc * 4];
    float4 bb4 = *(const float4*)bp;
#pragma unroll
    for (int i = 0; i < 2; i++) {
        float2 lo = unpack2(acc2[i][0]);
        float2 hi = unpack2(acc2[i][1]);
        float* crow = &C[(size_t)(i0 + tr * 2 + i) * ldc + o0 + tc * 4];
        *(float4*)crow = make_float4(lo.x + bb4.x, lo.y + bb4.y,
                                     hi.x + bb4.z, hi.y + bb4.w);
    }
}

// ---------- register-tiled GEMM: 64x64 tile, 4x4 per thread (final) ----------
__global__ void gemm64_kernel(const float* __restrict__ A, int lda,
                              const float* __restrict__ W, int ldw,
                              float* __restrict__ C, int ldc, int kLen)
{
    __shared__ float sA[16][68];
    __shared__ float sB[16][68];
    int i0 = blockIdx.x * 64;
    int o0 = blockIdx.y * 64;
    int k0 = blockIdx.z * kLen;
    C += (size_t)blockIdx.z * (size_t)(gridDim.x * 64) * ldc;

    int t  = threadIdx.x;
    int tc = t & 15;
    int tr = t >> 4;

    int ar = t >> 2;
    int ak = (t & 3) * 4;
    int bk = t >> 4;
    int bn = (t & 15) * 4;

    ull acc2[4][2];
#pragma unroll
    for (int i = 0; i < 4; i++) { acc2[i][0] = 0ull; acc2[i][1] = 0ull; }

    for (int kk = 0; kk < kLen; kk += 16) {
        __syncthreads();
        float4 av = *(const float4*)&A[(size_t)(i0 + ar) * lda + k0 + kk + ak];
        sA[ak + 0][ar] = av.x;
        sA[ak + 1][ar] = av.y;
        sA[ak + 2][ar] = av.z;
        sA[ak + 3][ar] = av.w;
        float4 bv = *(const float4*)&W[(size_t)(k0 + kk + bk) * ldw + o0 + bn];
        *(float4*)&sB[bk][bn] = bv;
        __syncthreads();
#pragma unroll
        for (int k = 0; k < 16; k++) {
            float4 a = *(const float4*)&sA[k][tr * 4];
            ulonglong2 b2 = *(const ulonglong2*)&sB[k][tc * 4];
            ull a0 = pack2(a.x, a.x);
            ull a1 = pack2(a.y, a.y);
            ull a2 = pack2(a.z, a.z);
            ull a3 = pack2(a.w, a.w);
            acc2[0][0] = ffma2(a0, b2.x, acc2[0][0]);
            acc2[0][1] = ffma2(a0, b2.y, acc2[0][1]);
            acc2[1][0] = ffma2(a1, b2.x, acc2[1][0]);
            acc2[1][1] = ffma2(a1, b2.y, acc2[1][1]);
            acc2[2][0] = ffma2(a2, b2.x, acc2[2][0]);
            acc2[2][1] = ffma2(a2, b2.y, acc2[2][1]);
            acc2[3][0] = ffma2(a3, b2.x, acc2[3][0]);
            acc2[3][1] = ffma2(a3, b2.y, acc2[3][1]);
        }
    }

#pragma unroll
    for (int i = 0; i < 4; i++) {
        float2 lo = unpack2(acc2[i][0]);
        float2 hi = unpack2(acc2[i][1]);
        float* crow = &C[(size_t)(i0 + tr * 4 + i) * ldc + o0 + tc * 4];
        *(float4*)crow = make_float4(lo.x, lo.y, hi.x, hi.y);
    }
}

// ---------------- split-K reduce + bias (float4) -----------------------------
__global__ void reduce_kernel(const float* __restrict__ bias,
                              float* __restrict__ out)
{
    int idx = blockIdx.x * blockDim.x + threadIdx.x;
    if (idx >= NROWS / 4) return;
    const float4* p = (const float4*)g_part;
    float4 a = p[idx];
    float4 b = p[idx + NROWS / 4];
    float4 c = p[idx + NROWS / 2];
    float4 d = p[idx + 3 * NROWS / 4];
    int col = (idx % (N_RESV / 4)) * 4;
    float4 bv = *(const float4*)&bias[col];
    float4 o;
    o.x = a.x + b.x + c.x + d.x + bv.x;
    o.y = a.y + b.y + c.y + d.y + bv.y;
    o.z = a.z + b.z + c.z + d.z + bv.z;
    o.w = a.w + b.w + c.w + d.w + bv.w;
    ((float4*)out)[idx] = o;
}

// ---------------- kernel 3: scatter projections + transform points -----------
__global__ void scatter_kernel(const float* __restrict__ T)
{
    int i = blockIdx.x;
    const float* raw = g_raw + (size_t)i * DPROJ;
    const float* Ti  = T + (size_t)i * 16;

    for (int t = threadIdx.x; t < 768; t += blockDim.x) {
        if (t < 576) {
            int kind = t / 192, d = t % 192;
            int h = d / 16, c = d % 16;
            float v = raw[kind * 192 + d];
            if (kind == 0) v *= 0.25f;
            float* dst = (kind == 0) ? g_q : ((kind == 1) ? g_k : g_v);
            dst[(h * N_RESV + i) * CHV + c] = v;
        } else {
            int t2 = t - 576;
            int kind, hp, P, base;
            if      (t2 < 48)  { kind = 0; hp = t2;       P = NQPV; base = 576; }
            else if (t2 < 96)  { kind = 1; hp = t2 - 48;  P = NQPV; base = 720; }
            else               { kind = 2; hp = t2 - 96;  P = NPVV; base = 864; }
            int HP = NHV * P;
            float px = raw[base + 0 * HP + hp];
            float py = raw[base + 1 * HP + hp];
            float pz = raw[base + 2 * HP + hp];
            float ox = Ti[0] * px + Ti[1] * py + Ti[2]  * pz + Ti[3];
            float oy = Ti[4] * px + Ti[5] * py + Ti[6]  * pz + Ti[7];
            float oz = Ti[8] * px + Ti[9] * py + Ti[10] * pz + Ti[11];
            float* dst = (kind == 0) ? g_tqp : ((kind == 1) ? g_tkp : g_tvp);
            float* o = dst + ((size_t)hp * N_RESV + i) * 3;
            o[0] = ox; o[1] = oy; o[2] = oz;
        }
    }
}

// ---------------- kernel 4: bias = z @ Wb + bb (double-buffered pipeline) ----
// grid 1152, block 128; 128 rows/block, 1 row/thread, 12 heads, one z pass.
// Chunked over 4x32 channels; next chunk's LDGs are in flight during compute.
__global__ void bias_gemm_kernel(const float* __restrict__ z,
                                 const float* __restrict__ Wb,
                                 const float* __restrict__ bb)
{
    __shared__ float2 sz[2][128 * 17];
    __shared__ ull    swp[NHV * 64];
    int t = threadIdx.x;
    int r0 = blockIdx.x * 128;

    for (int idx = t; idx < NHV * 64; idx += 128) {
        int h = idx >> 6, q = idx & 63;
        swp[idx] = pack2(Wb[(2 * q) * NHV + h], Wb[(2 * q + 1) * NHV + h]);
    }

    ull acc[NHV];
#pragma unroll
    for (int h = 0; h < NHV; h++) acc[h] = 0ull;

    float4 pre[8];
    // preload chunk 0 (coalesced: idx = t + k*128; row = idx/8, q4 = idx%8)
#pragma unroll
    for (int k = 0; k < 8; k++) {
        int idx = t + (k << 7);
        int row = idx >> 3, q4 = idx & 7;
        pre[k] = *(const float4*)&z[(size_t)(r0 + row) * CZV + (q4 << 2)];
    }
#pragma unroll
    for (int k = 0; k < 8; k++) {
        int idx = t + (k << 7);
        int row = idx >> 3, q4 = idx & 7;
        float2* d = &sz[0][row * 17 + q4 * 2];
        d[0] = make_float2(pre[k].x, pre[k].y);
        d[1] = make_float2(pre[k].z, pre[k].w);
    }
    __syncthreads();

#pragma unroll
    for (int c = 0; c < 4; c++) {
        if (c < 3) {
            int ct = (c + 1) << 5;
#pragma unroll
            for (int k = 0; k < 8; k++) {
                int idx = t + (k << 7);
                int row = idx >> 3, q4 = idx & 7;
                pre[k] = *(const float4*)&z[(size_t)(r0 + row) * CZV + ct + (q4 << 2)];
            }
        }
        const float2* zrow = &sz[c & 1][t * 17];
        int cbase = c << 4;
#pragma unroll
        for (int q = 0; q < 16; q++) {
            ull zp = *reinterpret_cast<const ull*>(&zrow[q]);
#pragma unroll
            for (int h = 0; h < NHV; h++)
                acc[h] = ffma2(zp, swp[(h << 6) + cbase + q], acc[h]);
        }
        if (c < 3) {
#pragma unroll
            for (int k = 0; k < 8; k++) {
                int idx = t + (k << 7);
                int row = idx >> 3, q4 = idx & 7;
                float2* d = &sz[(c + 1) & 1][row * 17 + q4 * 2];
                d[0] = make_float2(pre[k].x, pre[k].y);
                d[1] = make_float2(pre[k].z, pre[k].w);
            }
            __syncthreads();
        }
    }

    int row = r0 + t;
#pragma unroll
    for (int h = 0; h < NHV; h++) {
        float2 v = unpack2(acc[h]);
        g_bias[(size_t)h * NROWS + row] = v.x + v.y + bb[h];
    }
}

// ---------------- kernel 5: logits + softmax. grid (48, 12), block 256 -------
__global__ void att_kernel(const float* __restrict__ head_weights)
{
    int h = blockIdx.y;
    int i0 = blockIdx.x * 8;
    __shared__ float sk [32][17];
    __shared__ float skp[32][12];
    __shared__ float sq [8][16];
    __shared__ float sqp[8][12];
    __shared__ float slog[8][N_RESV];

    int t = threadIdx.x, w = t >> 5, lane = t & 31;

    if (t < 128) {
        int iw = t / 16, c = t % 16;
        sq[iw][c] = g_q[(h * N_RESV + i0 + iw) * CHV + c];
    }
    if (t < 96) {
        int iw = t / 12, u = t % 12, p = u / 3, d = u % 3;
        sqp[iw][u] = g_tqp[((h * NQPV + p) * N_RESV + i0 + iw) * 3 + d];
    }
    float hw = head_weights[h];
    float gamma = (hw > 20.f) ? hw : log1pf(expf(hw));
    const float wc = 0.23570226039551584f;
    const float wl = 0.57735026918962576f;
    float coef = gamma * wc * 0.5f;

    const float* brow = &g_bias[(size_t)h * NROWS + (size_t)(i0 + w) * N_RESV];

    for (int j0 = 0; j0 < N_RESV; j0 += 32) {
        __syncthreads();
        for (int idx = t; idx < 32 * 16; idx += 256)
            sk[idx >> 4][idx & 15] = g_k[(h * N_RESV + j0 + (idx >> 4)) * CHV + (idx & 15)];
        for (int idx = t; idx < 32 * 12; idx += 256) {
            int j = idx / 12, u = idx % 12, p = u / 3, d = u % 3;
            skp[j][u] = g_tkp[((h * NQPV + p) * N_RESV + j0 + j) * 3 + d];
        }
        __syncthreads();
        int j = j0 + lane;
        float qk = 0.f;
#pragma unroll
        for (int c = 0; c < CHV; c++) qk = fmaf(sq[w][c], sk[lane][c], qk);
        float d2 = 0.f;
#pragma unroll
        for (int p = 0; p < NQPV; p++) {
            float dx = sqp[w][p * 3 + 0] - skp[lane][p * 3 + 0];
            float dy = sqp[w][p * 3 + 1] - skp[lane][p * 3 + 1];
            float dz = sqp[w][p * 3 + 2] - skp[lane][p * 3 + 2];
            d2 += dx * dx + dy * dy + dz * dz;
        }
        slog[w][j] = wl * (qk + brow[j] - coef * d2);
    }

    float m = -1e30f;
#pragma unroll
    for (int r = 0; r < 12; r++) m = fmaxf(m, slog[w][lane + r * 32]);
#pragma unroll
    for (int o = 16; o; o >>= 1) m = fmaxf(m, __shfl_xor_sync(0xffffffffu, m, o));
    float ssum = 0.f;
#pragma unroll
    for (int r = 0; r < 12; r++) {
        float e = expf(slog[w][lane + r * 32] - m);
        slog[w][lane + r * 32] = e;
        ssum += e;
    }
#pragma unroll
    for (int o = 16; o; o >>= 1) ssum += __shfl_xor_sync(0xffffffffu, ssum, o);
    float inv = 1.f / ssum;
    float* arow = &g_att[(size_t)h * NROWS + (size_t)(i0 + w) * N_RESV];
#pragma unroll
    for (int r = 0; r < 12; r++) arow[lane + r * 32] = slog[w][lane + r * 32] * inv;
}

// ---------------- kernel 6: per-head GEMM  att[h] @ [v|vp], f32x2 ------------
// grid (12, 12) = 144 blocks, block 320; tile 32 rows x 40 cols; 4 cols/thread.
__global__ void att_av_kernel()
{
    int h = blockIdx.y;
    int i0 = blockIdx.x * 32;
    __shared__ float satt[32][65];
    __shared__ float sx[64][44];
    int t = threadIdx.x;
    int r  = t / 10;
    int c0 = (t % 10) * 4;
    ull acc2[2];
    acc2[0] = 0ull; acc2[1] = 0ull;

    for (int j0 = 0; j0 < N_RESV; j0 += 64) {
        __syncthreads();
        for (int idx = t; idx < 32 * 16; idx += 320) {
            int row = idx >> 4, v4 = idx & 15;
            float4 v = *(const float4*)&g_att[((size_t)h * N_RESV + i0 + row) * N_RESV + j0 + v4 * 4];
            float* dst = &satt[row][v4 * 4];
            dst[0] = v.x; dst[1] = v.y; dst[2] = v.z; dst[3] = v.w;
        }
        for (int idx = t; idx < 64 * 40; idx += 320) {
            int j = idx / 40, col = idx % 40;
            float v;
            if (col < 16) v = g_v[(h * N_RESV + j0 + j) * CHV + col];
            else {
                int u = col - 16, p = u / 3, d = u % 3;
                v = g_tvp[((h * NPVV + p) * N_RESV + j0 + j) * 3 + d];
            }
            sx[j][col] = v;
        }
        __syncthreads();
#pragma unroll 4
        for (int jj = 0; jj < 64; jj++) {
            float a = satt[r][jj];
            ull ap = pack2(a, a);
            ulonglong2 xr = *(const ulonglong2*)&sx[jj][c0];
            acc2[0] = ffma2(ap, xr.x, acc2[0]);
            acc2[1] = ffma2(ap, xr.y, acc2[1]);
        }
    }
    float2 lo = unpack2(acc2[0]);
    float2 hi = unpack2(acc2[1]);
    float* orow = &g_av[((size_t)h * N_RESV + i0 + r) * 40 + c0];
    *(float4*)orow = make_float4(lo.x, lo.y, hi.x, hi.y);
}

// ---------------- kernel 7: pairwise GEMM + finalize (direct-LDG, f32x2) -----
__global__ void out_kernel(const float* __restrict__ z,
                           const float* __restrict__ T)
{
    int i = blockIdx.x;
    __shared__ float att[NHV][N_RESV];
    int t = threadIdx.x;

    for (int idx = t; idx < NHV * N_RESV / 4; idx += 384) {
        int h = idx / (N_RESV / 4), q = idx % (N_RESV / 4);
        float4 v = *(const float4*)&g_att[((size_t)h * N_RESV + i) * N_RESV + q * 4];
        *(float4*)&att[h][q * 4] = v;
    }
    __syncthreads();

    int h  = t >> 5;
    int c4 = t & 31;
    const ulonglong2* zbase = (const ulonglong2*)(z + (size_t)i * N_RESV * CZV) + c4;
    const float* arow = att[h];

    ull acc01 = 0ull, acc23 = 0ull;
#pragma unroll 4
    for (int j = 0; j < N_RESV; j++) {
        float a = arow[j];
        ull ap = pack2(a, a);
        ulonglong2 zp = __ldg(zbase + (size_t)j * 32);
        acc01 = ffma2(ap, zp.x, acc01);
        acc23 = ffma2(ap, zp.y, acc23);
    }
    float2 lo = unpack2(acc01);
    float2 hi = unpack2(acc23);
    float* crow = g_concat + (size_t)i * DCAT;
    *(float4*)&crow[576 + h * CZV + c4 * 4] = make_float4(lo.x, lo.y, hi.x, hi.y);

    if (t < 192) {
        int hh = t / 16, cc = t % 16;
        crow[hh * 16 + cc] = g_av[((size_t)hh * N_RESV + i) * 40 + cc];
    }
    const float* Ti = T + (size_t)i * 16;
    if (t < 96) {
        int hh = t / 8, p = t % 8;
        const float* av = &g_av[((size_t)hh * N_RESV + i) * 40 + 16 + p * 3];
        float px = av[0] - Ti[3];
        float py = av[1] - Ti[7];
        float pz = av[2] - Ti[11];
        float ox = Ti[0] * px + Ti[4] * py + Ti[8]  * pz;
        float oy = Ti[1] * px + Ti[5] * py + Ti[9]  * pz;
        float oz = Ti[2] * px + Ti[6] * py + Ti[10] * pz;
        crow[192 +   0 + hh * 8 + p] = ox;
        crow[192 +  96 + hh * 8 + p] = oy;
        crow[192 + 192 + hh * 8 + p] = oz;
        crow[480 + hh * 8 + p] = sqrtf(ox * ox + oy * oy + oz * oz);
    }
}

// ---------------- launch ------------------------------------------------------
extern "C" void kernel_launch(void* const* d_in, const int* in_sizes, int n_in,
                              void* d_out, int out_size)
{
    const float* s   = (const float*)d_in[0];
    const float* z   = (const float*)d_in[1];
    const float* T   = (const float*)d_in[2];
    const float* Wq  = (const float*)d_in[3];
    const float* bq  = (const float*)d_in[4];
    const float* Wk  = (const float*)d_in[5];
    const float* bk  = (const float*)d_in[6];
    const float* Wv  = (const float*)d_in[7];
    const float* bv  = (const float*)d_in[8];
    const float* Wqp = (const float*)d_in[9];
    const float* bqp = (const float*)d_in[10];
    const float* Wkp = (const float*)d_in[11];
    const float* bkp = (const float*)d_in[12];
    const float* Wvp = (const float*)d_in[13];
    const float* bvp = (const float*)d_in[14];
    const float* Wb  = (const float*)d_in[15];
    const float* bb  = (const float*)d_in[16];
    const float* Wo  = (const float*)d_in[17];
    const float* bo  = (const float*)d_in[18];
    const float* hwt = (const float*)d_in[19];

    float* out = (float*)d_out;

    float* raw_p;    cudaGetSymbolAddress((void**)&raw_p,    g_raw);
    float* wcat_p;   cudaGetSymbolAddress((void**)&wcat_p,   g_Wcat);
    float* bcat_p;   cudaGetSymbolAddress((void**)&bcat_p,   g_bcat);
    float* concat_p; cudaGetSymbolAddress((void**)&concat_p, g_concat);
    float* part_p;   cudaGetSymbolAddress((void**)&part_p,   g_part);

    build_wcat_kernel<<<432, 256>>>(Wq, bq, Wk, bk, Wv, bv,
                                    Wqp, bqp, Wkp, bkp, Wvp, bvp);

    gemm32_kernel<<<dim3(N_RESV / 32, DPROJ / 64), 256>>>(
        s, CSV, wcat_p, DPROJ, bcat_p, raw_p, DPROJ, CSV);

    scatter_kernel<<<N_RESV, 256>>>(T);

    bias_gemm_kernel<<<NROWS / 128, 128>>>(z, Wb, bb);

    att_kernel<<<dim3(48, NHV), 256>>>(hwt);

    att_av_kernel<<<dim3(12, NHV), 320>>>();

    out_kernel<<<N_RESV, 384>>>(z, T);

    gemm64_kernel<<<dim3(N_RESV / 64, N_RESV / 64, SPLITK), 256>>>(
        concat_p, DCAT, Wo, CSV, part_p, CSV, KSLICE);

    reduce_kernel<<<(NROWS / 4 + 255) / 256, 256>>>(bo, out);
}